// round 1
// baseline (speedup 1.0000x reference)
#include <cuda_runtime.h>
#include <mma.h>

using namespace nvcuda;

// Problem constants
#define TOK  16384   // B*S tokens
#define DIM  1024    // d_model (K)
#define OUTD 4096    // out dim (N)

// Tiling
#define BM 128
#define BN 64
#define BK 16
#define NTHREADS 256

// Shared layout: staging tiles for the mainloop, reused as epilogue staging.
struct SharedStage {
    float Xs[BM][24];       // X tile, row-major [m][k], tf32 bits, pad to 24
    float Ws[2][BN][28];    // W tiles transposed [n][k] for col_major b-frags, pad 28
};
union __align__(16) SharedU {
    SharedStage st;
    float Cs[BM * BN];      // 32 KB epilogue staging (>= sizeof(SharedStage))
};

__global__ void __launch_bounds__(NTHREADS)
mot_dual_gemm_tf32(const float* __restrict__ X,
                   const int*   __restrict__ tids,
                   const float* __restrict__ W0,
                   const float* __restrict__ b0,
                   const float* __restrict__ W1,
                   const float* __restrict__ b1,
                   float* __restrict__ out)
{
    __shared__ SharedU su;

    const int tid    = threadIdx.x;
    const int warp   = tid >> 5;
    const int warp_m = warp >> 1;   // 0..3  (rows of 32)
    const int warp_n = warp & 1;    // 0..1  (cols of 32)
    const int token0 = blockIdx.y * BM;
    const int col0   = blockIdx.x * BN;

    // Accumulators: [expert][mi][nj], each 16x16 fp32
    wmma::fragment<wmma::accumulator, 16, 16, 8, float> acc[2][2][2];
#pragma unroll
    for (int e = 0; e < 2; e++)
#pragma unroll
        for (int i = 0; i < 2; i++)
#pragma unroll
            for (int j = 0; j < 2; j++)
                wmma::fill_fragment(acc[e][i][j], 0.0f);

    const float* Wp[2] = {W0, W1};

    for (int kk = 0; kk < DIM; kk += BK) {
        // ---- Load X tile: 128 x 16, coalesced along k ----
#pragma unroll
        for (int i = 0; i < (BM * BK) / NTHREADS; i++) {
            int idx = tid + i * NTHREADS;       // 0..2047
            int r = idx >> 4;                   // row (token)
            int k = idx & 15;                   // k within tile
            su.st.Xs[r][k] =
                wmma::__float_to_tf32(X[(size_t)(token0 + r) * DIM + kk + k]);
        }
        // ---- Load both W tiles: 16 x 64 each, stored transposed [n][k] ----
#pragma unroll
        for (int e = 0; e < 2; e++) {
            const float* __restrict__ W = Wp[e];
#pragma unroll
            for (int i = 0; i < (BK * BN) / NTHREADS; i++) {
                int idx = tid + i * NTHREADS;   // 0..1023
                int r = idx >> 6;               // k row
                int c = idx & 63;               // n col
                su.st.Ws[e][c][r] =
                    wmma::__float_to_tf32(W[(size_t)(kk + r) * OUTD + col0 + c]);
            }
        }
        __syncthreads();

        // ---- Two k=8 MMA steps ----
#pragma unroll
        for (int ks = 0; ks < BK; ks += 8) {
            wmma::fragment<wmma::matrix_a, 16, 16, 8, wmma::precision::tf32,
                           wmma::row_major> af[2];
#pragma unroll
            for (int i = 0; i < 2; i++)
                wmma::load_matrix_sync(af[i], &su.st.Xs[warp_m * 32 + i * 16][ks], 24);

            wmma::fragment<wmma::matrix_b, 16, 16, 8, wmma::precision::tf32,
                           wmma::col_major> bf[2][2];
#pragma unroll
            for (int e = 0; e < 2; e++)
#pragma unroll
                for (int j = 0; j < 2; j++)
                    wmma::load_matrix_sync(bf[e][j],
                                           &su.st.Ws[e][warp_n * 32 + j * 16][ks], 28);

#pragma unroll
            for (int e = 0; e < 2; e++)
#pragma unroll
                for (int i = 0; i < 2; i++)
#pragma unroll
                    for (int j = 0; j < 2; j++)
                        wmma::mma_sync(acc[e][i][j], af[i], bf[e][j], acc[e][i][j]);
        }
        __syncthreads();
    }

    // ---- Epilogue: per expert, stage to shared, add bias, mask, write ----
    const float* biasp[2] = {b0, b1};
#pragma unroll
    for (int e = 0; e < 2; e++) {
#pragma unroll
        for (int i = 0; i < 2; i++)
#pragma unroll
            for (int j = 0; j < 2; j++)
                wmma::store_matrix_sync(
                    &su.Cs[(warp_m * 32 + i * 16) * BN + warp_n * 32 + j * 16],
                    acc[e][i][j], BN, wmma::mem_row_major);
        __syncthreads();

        float* __restrict__ oute = out + (size_t)e * TOK * OUTD;
        const float* __restrict__ bias = biasp[e];
        const float4* Cs4 = reinterpret_cast<const float4*>(su.Cs);
#pragma unroll
        for (int i = 0; i < (BM * BN / 4) / NTHREADS; i++) {
            int idx = tid + i * NTHREADS;       // 0..2047 float4s
            int r  = idx >> 4;                  // row in tile
            int c4 = idx & 15;                  // float4 col index
            int token = token0 + r;
            int col   = col0 + c4 * 4;
            float4 v = Cs4[idx];
            float4 bb = *reinterpret_cast<const float4*>(bias + col);
            float m = (tids[token] == e) ? 1.0f : 0.0f;
            float4 o;
            o.x = (v.x + bb.x) * m;
            o.y = (v.y + bb.y) * m;
            o.z = (v.z + bb.z) * m;
            o.w = (v.w + bb.w) * m;
            *reinterpret_cast<float4*>(oute + (size_t)token * OUTD + col) = o;
        }
        __syncthreads();
    }
}

extern "C" void kernel_launch(void* const* d_in, const int* in_sizes, int n_in,
                              void* d_out, int out_size)
{
    const float* X   = (const float*)d_in[0];   // [B,S,D] fp32
    const int*   tid = (const int*)  d_in[1];   // [B,S] int32
    const float* W0  = (const float*)d_in[2];   // [D,OUT]
    const float* b0  = (const float*)d_in[3];   // [OUT]
    const float* W1  = (const float*)d_in[4];   // [D,OUT]
    const float* b1  = (const float*)d_in[5];   // [OUT]
    float* out = (float*)d_out;                 // [2, B, S, OUT]

    dim3 grid(OUTD / BN, TOK / BM);             // (64, 128)
    mot_dual_gemm_tf32<<<grid, NTHREADS>>>(X, tid, W0, b0, W1, b1, out);
}

// round 3
// speedup vs baseline: 2.4175x; 2.4175x over previous
#include <cuda_runtime.h>
#include <mma.h>
#include <cstdint>

using namespace nvcuda;

// ---------------- Problem constants ----------------
#define TOK  16384
#define DIM  1024
#define OUTD 4096

// ---------------- GEMM tiling ----------------
#define BM 256
#define BN 128
#define BK 32
#define NTHREADS 256
#define NCHUNK (DIM / BK)      // 32

// smem stage layout (floats, padded rows of 36)
#define ROWPAD 36
#define XS_BYTES (BM * ROWPAD * 4)          // 36864
#define WS_BYTES (BN * ROWPAD * 4)          // 18432
#define STAGE_BYTES (XS_BYTES + WS_BYTES)   // 55296
#define SMEM_TOTAL (2 * STAGE_BYTES)        // 110592

// ---------------- Device scratch ----------------
__device__ float g_Xr[TOK * DIM];           // tf32-rounded X (64 MiB)
__device__ float g_Wt[2][OUTD][DIM];        // tf32-rounded W^T (32 MiB)
__device__ int   g_perm[2 * TOK];           // routed token lists
__device__ int   g_cnt[2];

// ---------------- small helpers ----------------
__device__ __forceinline__ uint32_t smem_u32(const void* p) {
    uint32_t a;
    asm("{ .reg .u64 t; cvta.to.shared.u64 t, %1; cvt.u32.u64 %0, t; }" : "=r"(a) : "l"(p));
    return a;
}
__device__ __forceinline__ void cp16(uint32_t dst, const void* src) {
    asm volatile("cp.async.cg.shared.global [%0], [%1], 16;" :: "r"(dst), "l"(src));
}
#define CP_COMMIT() asm volatile("cp.async.commit_group;" ::: "memory")
#define CP_WAIT(n)  asm volatile("cp.async.wait_group %0;" :: "n"(n) : "memory")

// ---------------- Prep kernels ----------------
__global__ void zero_cnt() { if (threadIdx.x < 2) g_cnt[threadIdx.x] = 0; }

__global__ void compact_tokens(const int* __restrict__ tids) {
    int t = blockIdx.x * blockDim.x + threadIdx.x;   // 16384 threads
    int e = tids[t];
    int lane = threadIdx.x & 31;
    unsigned m1 = __ballot_sync(0xffffffffu, e == 1);
    unsigned me = (e == 1) ? m1 : ~m1;
    int leader = __ffs(me) - 1;
    int base = 0;
    if (lane == leader) base = atomicAdd(&g_cnt[e], __popc(me));
    base = __shfl_sync(0xffffffffu, base, leader);
    int pos = base + __popc(me & ((1u << lane) - 1u));
    g_perm[e * TOK + pos] = t;
}

__global__ void round_x(const float4* __restrict__ X) {
    int i = blockIdx.x * blockDim.x + threadIdx.x;   // TOK*DIM/4 threads
    float4 v = X[i];
    v.x = wmma::__float_to_tf32(v.x);
    v.y = wmma::__float_to_tf32(v.y);
    v.z = wmma::__float_to_tf32(v.z);
    v.w = wmma::__float_to_tf32(v.w);
    ((float4*)g_Xr)[i] = v;
}

__global__ void transpose_w(const float* __restrict__ W0, const float* __restrict__ W1) {
    __shared__ float t[32][33];
    const float* __restrict__ W = blockIdx.z ? W1 : W0;
    int n0 = blockIdx.x * 32, k0 = blockIdx.y * 32;
#pragma unroll
    for (int i = threadIdx.y; i < 32; i += 8)
        t[i][threadIdx.x] =
            wmma::__float_to_tf32(W[(size_t)(k0 + i) * OUTD + n0 + threadIdx.x]);
    __syncthreads();
    float* __restrict__ Wt = &g_Wt[blockIdx.z][0][0];
#pragma unroll
    for (int i = threadIdx.y; i < 32; i += 8)
        Wt[(size_t)(n0 + i) * DIM + k0 + threadIdx.x] = t[threadIdx.x][i];
}

// ---------------- Main routed GEMM ----------------
__global__ void __launch_bounds__(NTHREADS, 1)
mot_routed_gemm(const float* __restrict__ b0,
                const float* __restrict__ b1,
                float* __restrict__ out)
{
    const int e    = blockIdx.y >> 6;        // expert (grid.y = 128)
    const int tile = blockIdx.y & 63;        // row tile within expert
    const int col0 = blockIdx.x * BN;
    const int cnt  = g_cnt[e];
    const int row0 = tile * BM;
    if (row0 >= cnt) return;

    extern __shared__ char dynsm[];
    __shared__ int   tokS[BM];
    __shared__ float biasS[BN];

    const int tid  = threadIdx.x;
    const int warp = tid >> 5;
    const int warp_m = warp >> 1;            // 0..3 -> rows warp_m*64
    const int warp_n = warp & 1;             // 0..1 -> cols warp_n*64

    // token list + bias
    {
        int r = row0 + tid;
        tokS[tid] = (r < cnt) ? g_perm[e * TOK + r] : 0;
        if (tid < BN) biasS[tid] = (e ? b1 : b0)[col0 + tid];
    }
    __syncthreads();

    // per-thread fixed load coordinates
    const int lr = tid >> 3;                 // 0..31 (row group base)
    const int lc = tid & 7;                  // 16B chunk within 128B row
    int myTok[8];
#pragma unroll
    for (int j = 0; j < 8; j++) myTok[j] = tokS[lr + 32 * j];

    const uint32_t sm = smem_u32(dynsm);
    const float* __restrict__ Wtp = &g_Wt[e][col0][0];

    auto load_stage = [&](int s, int kk) {
        const uint32_t xs = sm + s * STAGE_BYTES;
        const uint32_t ws = xs + XS_BYTES;
#pragma unroll
        for (int j = 0; j < 8; j++) {
            int row = lr + 32 * j;
            cp16(xs + (uint32_t)(row * (ROWPAD * 4) + lc * 16),
                 g_Xr + (size_t)myTok[j] * DIM + kk + lc * 4);
        }
#pragma unroll
        for (int j = 0; j < 4; j++) {
            int n = lr + 32 * j;
            cp16(ws + (uint32_t)(n * (ROWPAD * 4) + lc * 16),
                 Wtp + (size_t)n * DIM + kk + lc * 4);
        }
    };

    // accumulators
    wmma::fragment<wmma::accumulator, 16, 16, 8, float> acc[4][4];
#pragma unroll
    for (int i = 0; i < 4; i++)
#pragma unroll
        for (int j = 0; j < 4; j++) wmma::fill_fragment(acc[i][j], 0.0f);

    // pipeline
    load_stage(0, 0);
    CP_COMMIT();

    for (int c = 0; c < NCHUNK; c++) {
        if (c + 1 < NCHUNK) {
            load_stage((c + 1) & 1, (c + 1) * BK);
            CP_COMMIT();
            CP_WAIT(1);
        } else {
            CP_WAIT(0);
        }
        __syncthreads();

        const float* xb = (const float*)(dynsm + (c & 1) * STAGE_BYTES);
        const float* wb = xb + BM * ROWPAD;
#pragma unroll
        for (int ks = 0; ks < 4; ks++) {
            wmma::fragment<wmma::matrix_a, 16, 16, 8, wmma::precision::tf32,
                           wmma::row_major> af[4];
            wmma::fragment<wmma::matrix_b, 16, 16, 8, wmma::precision::tf32,
                           wmma::col_major> bf[4];
#pragma unroll
            for (int i = 0; i < 4; i++)
                wmma::load_matrix_sync(af[i],
                    xb + (warp_m * 64 + i * 16) * ROWPAD + ks * 8, ROWPAD);
#pragma unroll
            for (int j = 0; j < 4; j++)
                wmma::load_matrix_sync(bf[j],
                    wb + (warp_n * 64 + j * 16) * ROWPAD + ks * 8, ROWPAD);
#pragma unroll
            for (int i = 0; i < 4; i++)
#pragma unroll
                for (int j = 0; j < 4; j++)
                    wmma::mma_sync(acc[i][j], af[i], bf[j], acc[i][j]);
        }
        __syncthreads();
    }

    // ---- Epilogue: two 128x128 halves staged through smem ----
    float* Cs = (float*)dynsm;               // 128*128 floats = 64 KB
    float* __restrict__ oute = out + (size_t)e * TOK * OUTD;
    float* __restrict__ outo = out + (size_t)(1 - e) * TOK * OUTD;

#pragma unroll
    for (int h = 0; h < 2; h++) {
        if ((warp_m >> 1) == h) {
            int lm = (warp_m & 1) * 64;
#pragma unroll
            for (int i = 0; i < 4; i++)
#pragma unroll
                for (int j = 0; j < 4; j++)
                    wmma::store_matrix_sync(
                        Cs + (lm + i * 16) * BN + warp_n * 64 + j * 16,
                        acc[i][j], BN, wmma::mem_row_major);
        }
        __syncthreads();

#pragma unroll
        for (int q = 0; q < 16; q++) {
            int idx = tid + q * NTHREADS;    // float4 index, 0..4095
            int r  = idx >> 5;               // 0..127
            int c4 = idx & 31;
            int grow = h * 128 + r;
            if (row0 + grow < cnt) {
                int token = tokS[grow];
                float4 v = ((const float4*)Cs)[idx];
                float4 bb = *(const float4*)&biasS[c4 * 4];
                v.x += bb.x; v.y += bb.y; v.z += bb.z; v.w += bb.w;
                *(float4*)(oute + ((size_t)token * OUTD) + col0 + c4 * 4) = v;
                float4 z = make_float4(0.f, 0.f, 0.f, 0.f);
                *(float4*)(outo + ((size_t)token * OUTD) + col0 + c4 * 4) = z;
            }
        }
        __syncthreads();
    }
}

// ---------------- Launch ----------------
extern "C" void kernel_launch(void* const* d_in, const int* in_sizes, int n_in,
                              void* d_out, int out_size)
{
    const float* X   = (const float*)d_in[0];
    const int*   tid = (const int*)  d_in[1];
    const float* W0  = (const float*)d_in[2];
    const float* b0  = (const float*)d_in[3];
    const float* W1  = (const float*)d_in[4];
    const float* b1  = (const float*)d_in[5];
    float* out = (float*)d_out;

    cudaFuncSetAttribute(mot_routed_gemm,
                         cudaFuncAttributeMaxDynamicSharedMemorySize, SMEM_TOTAL);

    zero_cnt<<<1, 32>>>();
    compact_tokens<<<TOK / 256, 256>>>(tid);
    round_x<<<(TOK * DIM / 4) / 256, 256>>>((const float4*)X);
    transpose_w<<<dim3(OUTD / 32, DIM / 32, 2), dim3(32, 8)>>>(W0, W1);

    dim3 grid(OUTD / BN, 128);               // 32 x (2 experts * 64 row tiles)
    mot_routed_gemm<<<grid, NTHREADS, SMEM_TOTAL>>>(b0, b1, out);
}